// round 1
// baseline (speedup 1.0000x reference)
#include <cuda_runtime.h>
#include <cuda_bf16.h>
#include <mma.h>

using namespace nvcuda;

#define MDIM  128
#define FEAT  8256          // MDIM*(MDIM+1)/2
#define HID   1651          // FEAT // 5
#define NP    1664          // HID padded to multiple of 64
#define BATCH 4096

// ---------------- device scratch (no allocations allowed) ----------------
__device__ __nv_bfloat16 g_x [(size_t)BATCH * FEAT];   // 67.6 MB
__device__ __nv_bfloat16 g_w1[(size_t)NP    * FEAT];   // 27.5 MB (padded rows = 0)
__device__ float g_b1[NP];
__device__ float g_w2[NP];
__device__ float g_logits[BATCH];

// ---------------- prep: small vectors + logit zeroing ----------------
__global__ void prep_small(const float* __restrict__ b1, const float* __restrict__ w2) {
    int i = blockIdx.x * blockDim.x + threadIdx.x;
    if (i < NP) {
        g_b1[i] = (i < HID) ? b1[i] : 0.0f;
        g_w2[i] = (i < HID) ? w2[i] : 0.0f;
    }
    if (i < BATCH) g_logits[i] = 0.0f;
}

// ---------------- prep: W1 fp32 -> bf16, pad rows [HID, NP) with zeros ----------------
__global__ void prep_w1(const float* __restrict__ W1) {
    int n = blockIdx.y;
    int k = blockIdx.x * blockDim.x + threadIdx.x;
    if (k >= FEAT) return;
    float v = (n < HID) ? W1[(size_t)n * FEAT + k] : 0.0f;
    g_w1[(size_t)n * FEAT + k] = __float2bfloat16(v);
}

// ---------------- triu extraction: sim[b, i, j>=i] -> x_bf16[b, idx] ----------------
__global__ void triu_kernel(const float* __restrict__ sim) {
    int b = blockIdx.y;
    int i = blockIdx.x;
    int j = threadIdx.x;
    if (j < i) return;
    int rowoff = i * MDIM - (i * (i - 1)) / 2;  // start of row i in packed triu order
    float v = sim[((size_t)b * MDIM + i) * MDIM + j];
    g_x[(size_t)b * FEAT + rowoff + (j - i)] = __float2bfloat16(v);
}

// ---------------- fused GEMM: logits[b] += sum_n relu(x@W1^T + b1)[b,n] * w2[n] ----------------
// Block tile: 128(M) x 64(N), K step 64. 8 warps in 4(M) x 2(N); warp tile 32x32 (2x2 wmma frags).
__global__ __launch_bounds__(256) void gemm_fused() {
    constexpr int BM = 128, BN = 64, BK = 64;
    constexpr int LDA = 72;   // bf16 smem stride (pad vs 64)
    constexpr int LDC = 68;   // f32  smem stride

    __shared__ __align__(16) union {
        struct { __nv_bfloat16 A[BM][LDA]; __nv_bfloat16 B[BN][LDA]; } s;
        float C[BM][LDC];
    } sm;

    const int tid  = threadIdx.x;
    const int warp = tid >> 5;
    const int wm   = warp & 3;   // warp row   (0..3)  -> 32 rows each
    const int wn   = warp >> 2;  // warp col   (0..1)  -> 32 cols each
    const int m0   = blockIdx.y * BM;
    const int n0   = blockIdx.x * BN;

    wmma::fragment<wmma::accumulator, 16, 16, 16, float> acc[2][2];
#pragma unroll
    for (int i = 0; i < 2; i++)
#pragma unroll
        for (int j = 0; j < 2; j++)
            wmma::fill_fragment(acc[i][j], 0.0f);

    for (int k0 = 0; k0 < FEAT; k0 += BK) {
        // Load A tile (128x64 bf16): 1024 x 16B vectors, 4 per thread
#pragma unroll
        for (int i = 0; i < 4; i++) {
            int v = tid + i * 256;
            int r = v >> 3;
            int c = (v & 7) * 8;
            *(uint4*)&sm.s.A[r][c] =
                *(const uint4*)&g_x[(size_t)(m0 + r) * FEAT + k0 + c];
        }
        // Load B tile (64x64 bf16 = W1 rows): 512 vectors, 2 per thread
#pragma unroll
        for (int i = 0; i < 2; i++) {
            int v = tid + i * 256;
            int r = v >> 3;
            int c = (v & 7) * 8;
            *(uint4*)&sm.s.B[r][c] =
                *(const uint4*)&g_w1[(size_t)(n0 + r) * FEAT + k0 + c];
        }
        __syncthreads();

#pragma unroll
        for (int kk = 0; kk < BK; kk += 16) {
            wmma::fragment<wmma::matrix_a, 16, 16, 16, __nv_bfloat16, wmma::row_major> af[2];
            wmma::fragment<wmma::matrix_b, 16, 16, 16, __nv_bfloat16, wmma::col_major> bf[2];
            wmma::load_matrix_sync(af[0], &sm.s.A[wm * 32][kk],      LDA);
            wmma::load_matrix_sync(af[1], &sm.s.A[wm * 32 + 16][kk], LDA);
            // B stored as [n][k]; col_major fragment: element (k,n) at base[n*ldm + k]
            wmma::load_matrix_sync(bf[0], &sm.s.B[wn * 32][kk],      LDA);
            wmma::load_matrix_sync(bf[1], &sm.s.B[wn * 32 + 16][kk], LDA);
#pragma unroll
            for (int i = 0; i < 2; i++)
#pragma unroll
                for (int j = 0; j < 2; j++)
                    wmma::mma_sync(acc[i][j], af[i], bf[j], acc[i][j]);
        }
        __syncthreads();
    }

    // Stage C tile to shared for the fused epilogue
#pragma unroll
    for (int i = 0; i < 2; i++)
#pragma unroll
        for (int j = 0; j < 2; j++)
            wmma::store_matrix_sync(&sm.C[wm * 32 + i * 16][wn * 32 + j * 16],
                                    acc[i][j], LDC, wmma::mem_row_major);
    __syncthreads();

    // Epilogue: per output row, relu(c + b1) * w2 reduced over the 64-col tile.
    // 256 threads: thread handles (row = tid/2, half = tid%2) -> 32 cols each.
    const int row  = tid >> 1;
    const int half = tid & 1;
    float s = 0.0f;
#pragma unroll
    for (int c = 0; c < 32; c++) {
        int col = half * 32 + c;
        int n   = n0 + col;
        float v = sm.C[row][col] + g_b1[n];
        s += fmaxf(v, 0.0f) * g_w2[n];
    }
    atomicAdd(&g_logits[m0 + row], s);
}

// ---------------- finalize: sigmoid ----------------
__global__ void finalize(const float* __restrict__ b2, float* __restrict__ out) {
    int i = blockIdx.x * blockDim.x + threadIdx.x;
    if (i < BATCH) {
        float z = g_logits[i] + b2[0];
        out[i] = 1.0f / (1.0f + expf(-z));
    }
}

// ---------------- launch ----------------
extern "C" void kernel_launch(void* const* d_in, const int* in_sizes, int n_in,
                              void* d_out, int out_size) {
    const float* sim = (const float*)d_in[0];
    const float* W1  = (const float*)d_in[1];
    const float* b1  = (const float*)d_in[2];
    const float* W2  = (const float*)d_in[3];
    const float* b2  = (const float*)d_in[4];
    float* out = (float*)d_out;

    prep_small<<<(BATCH + 255) / 256, 256>>>(b1, W2);
    prep_w1<<<dim3((FEAT + 255) / 256, NP), 256>>>(W1);
    triu_kernel<<<dim3(MDIM, BATCH), MDIM>>>(sim);
    gemm_fused<<<dim3(NP / 64, BATCH / 128), 256>>>();
    finalize<<<(BATCH + 255) / 256, 256>>>(b2, out);
}

// round 3
// speedup vs baseline: 1.9484x; 1.9484x over previous
#include <cuda_runtime.h>
#include <cuda_bf16.h>
#include <cuda_fp8.h>
#include <cstdint>

#define MDIM  128
#define FEAT  8256          // MDIM*(MDIM+1)/2
#define HID   1651
#define NP    1792          // HID padded to 14*128
#define KP    8320          // FEAT padded to 65*128 (bytes, fp8)
#define BATCH 4096
#define KST   65            // KP / 128

#define SCALE_W   8192.0f   // 2^13 applied to W1 before fp8
#define INV_S     (1.0f/8192.0f)

#define STAGE_BYTES 32768   // A: 128 rows x 128B (16KB) + B: 128 x 128B (16KB)
#define B_OFF       16384
#define NSTAGE      3
#define SMEM_TOTAL  (NSTAGE * STAGE_BYTES)

// ---------------- device scratch ----------------
__device__ uint8_t g_x8 [(size_t)BATCH * KP];   // 34.1 MB fp8
__device__ uint8_t g_w18[(size_t)NP    * KP];   // 14.9 MB fp8 (pad rows/cols = 0)
__device__ float g_b1[NP];
__device__ float g_w2[NP];
__device__ float g_logits[BATCH];

// ---------------- helpers ----------------
__device__ __forceinline__ uint32_t smem_u32(const void* p) {
    uint32_t a;
    asm("{ .reg .u64 t; cvta.to.shared.u64 t, %1; cvt.u32.u64 %0, t; }" : "=r"(a) : "l"(p));
    return a;
}
#define SWZ128(off) ((off) ^ (((off) >> 3) & 0x70))

__device__ __forceinline__ void ldsm_x4(uint32_t& r0, uint32_t& r1, uint32_t& r2, uint32_t& r3,
                                        uint32_t addr) {
    asm volatile("ldmatrix.sync.aligned.m8n8.x4.shared.b16 {%0,%1,%2,%3}, [%4];"
                 : "=r"(r0), "=r"(r1), "=r"(r2), "=r"(r3) : "r"(addr));
}
__device__ __forceinline__ void mma_e4m3(float* c, const uint32_t* a, const uint32_t* b) {
    asm volatile(
        "mma.sync.aligned.m16n8k32.row.col.f32.e4m3.e4m3.f32 "
        "{%0,%1,%2,%3}, {%4,%5,%6,%7}, {%8,%9}, {%0,%1,%2,%3};"
        : "+f"(c[0]), "+f"(c[1]), "+f"(c[2]), "+f"(c[3])
        : "r"(a[0]), "r"(a[1]), "r"(a[2]), "r"(a[3]), "r"(b[0]), "r"(b[1]));
}

// ---------------- prep kernels ----------------
__global__ void prep_small(const float* __restrict__ b1, const float* __restrict__ w2) {
    int i = blockIdx.x * blockDim.x + threadIdx.x;
    if (i < NP) {
        g_b1[i] = (i < HID) ? b1[i] : 0.0f;
        g_w2[i] = (i < HID) ? w2[i] : 0.0f;
    }
    if (i < BATCH) g_logits[i] = 0.0f;
}

// W1 fp32 -> fp8 (scaled), rows [HID,NP) and cols [FEAT,KP) zero. 4 bytes/thread.
__global__ void prep_w18(const float* __restrict__ W1) {
    int n  = blockIdx.y;
    int k4 = blockIdx.x * blockDim.x + threadIdx.x;
    if (k4 >= KP / 4) return;
    uint32_t out = 0;
    if (n < HID) {
#pragma unroll
        for (int j = 0; j < 4; j++) {
            int k = k4 * 4 + j;
            float v = (k < FEAT) ? W1[(size_t)n * FEAT + k] * SCALE_W : 0.0f;
            out |= (uint32_t)__nv_cvt_float_to_fp8(v, __NV_SATFINITE, __NV_E4M3) << (8 * j);
        }
    }
    ((uint32_t*)g_w18)[(size_t)n * (KP / 4) + k4] = out;
}

// triu extraction fused with fp8 convert; zeroes the K pad.
__global__ __launch_bounds__(256) void triu8(const float* __restrict__ sim) {
    int b    = blockIdx.x;
    int tid  = threadIdx.x;
    int half = tid >> 7;
    int j    = tid & 127;
    const float* base = sim + (size_t)b * MDIM * MDIM;
    uint8_t* out = g_x8 + (size_t)b * KP;
#pragma unroll 4
    for (int it = 0; it < 64; ++it) {
        int i = it * 2 + half;
        if (j >= i) {
            float v = base[i * MDIM + j];
            int rowoff = i * MDIM - (i * (i - 1)) / 2;
            out[rowoff + j - i] = __nv_cvt_float_to_fp8(v, __NV_SATFINITE, __NV_E4M3);
        }
    }
    if (tid < KP - FEAT) out[FEAT + tid] = 0;
}

// ---------------- fp8 mma.sync GEMM, CTA 128x128, 3-stage cp.async, fused epilogue ----------------
__global__ __launch_bounds__(256, 2) void gemm_fp8() {
    extern __shared__ __align__(1024) uint8_t smem[];
    const uint32_t sbase = smem_u32(smem);
    const int tid = threadIdx.x;
    const int wid = tid >> 5;
    const int lid = tid & 31;
    const int wm  = wid & 3;            // warp M index: 4 x 32 rows
    const int wn  = wid >> 2;           // warp N index: 2 x 64 cols
    const int m0  = blockIdx.y * 128;
    const int n0  = blockIdx.x * 128;

    // per-thread ldmatrix source offsets (within tile, before swizzle)
    const int lr   = lid & 7;           // row within 8x8 matrix
    // A: mat = lid>>3: row += (mat&1)*8, colByte += (mat>>1)*16
    const int aRow0 = wm * 32 + ((lid >> 3) & 1) * 8 + lr;        // + mi*16
    const int aCol  = (lid >> 4) * 16;
    // B: mat = lid>>3: row += (mat>>1)*8, colByte += (mat&1)*16
    const int bRow0 = wn * 64 + (lid >> 4) * 8 + lr;              // + p*16
    const int bCol  = ((lid >> 3) & 1) * 16;

    float acc[2][8][4];
#pragma unroll
    for (int mi = 0; mi < 2; mi++)
#pragma unroll
        for (int ni = 0; ni < 8; ni++)
#pragma unroll
            for (int c = 0; c < 4; c++) acc[mi][ni][c] = 0.0f;

    // -------- producer --------
    auto load_stage = [&](int buf, int kByte) {
        uint32_t st = sbase + buf * STAGE_BYTES;
#pragma unroll
        for (int it = 0; it < 8; ++it) {
            int idx = tid + it * 256;           // 0..2047 16B chunks
            int isB = idx >> 10;
            int r   = (idx >> 3) & 127;
            int c   = idx & 7;
            const uint8_t* src = isB
                ? &g_w18[(size_t)(n0 + r) * KP + kByte + c * 16]
                : &g_x8 [(size_t)(m0 + r) * KP + kByte + c * 16];
            uint32_t dst = st + (isB ? B_OFF : 0) + SWZ128((uint32_t)(r * 128 + c * 16));
            asm volatile("cp.async.cg.shared.global [%0], [%1], 16;"
                         :: "r"(dst), "l"(src) : "memory");
        }
        asm volatile("cp.async.commit_group;" ::: "memory");
    };

    load_stage(0, 0);
    load_stage(1, 128);

    for (int s = 0; s < KST; ++s) {
        asm volatile("cp.async.wait_group 1;" ::: "memory");
        __syncthreads();

        if (s + 2 < KST) load_stage((s + 2) % NSTAGE, (s + 2) * 128);
        else             asm volatile("cp.async.commit_group;" ::: "memory");

        uint32_t Ab = sbase + (s % NSTAGE) * STAGE_BYTES;
        uint32_t Bb = Ab + B_OFF;

#pragma unroll
        for (int ks = 0; ks < 4; ++ks) {
            uint32_t a[2][4];
#pragma unroll
            for (int mi = 0; mi < 2; mi++) {
                uint32_t off = (uint32_t)((aRow0 + mi * 16) * 128 + ks * 32 + aCol);
                ldsm_x4(a[mi][0], a[mi][1], a[mi][2], a[mi][3], Ab + SWZ128(off));
            }
            uint32_t b[8][2];
#pragma unroll
            for (int p = 0; p < 4; p++) {
                uint32_t off = (uint32_t)((bRow0 + p * 16) * 128 + ks * 32 + bCol);
                uint32_t r0, r1, r2, r3;
                ldsm_x4(r0, r1, r2, r3, Bb + SWZ128(off));
                b[2 * p][0] = r0; b[2 * p][1] = r1;
                b[2 * p + 1][0] = r2; b[2 * p + 1][1] = r3;
            }
#pragma unroll
            for (int mi = 0; mi < 2; mi++)
#pragma unroll
                for (int ni = 0; ni < 8; ni++)
                    mma_e4m3(acc[mi][ni], a[mi], b[ni]);
        }
    }

    // -------- fused epilogue: logits[m] += sum_n relu(acc/S + b1[n]) * w2[n] --------
    const int qrow = lid >> 2;
    const int qcol = lid & 3;
    float rs[4] = {0.f, 0.f, 0.f, 0.f};   // [mi*2 + (0: row qrow, 1: row qrow+8)]
#pragma unroll
    for (int ni = 0; ni < 8; ni++) {
        int n = n0 + wn * 64 + ni * 8 + qcol * 2;
        float b1a = g_b1[n],     w2a = g_w2[n];
        float b1b = g_b1[n + 1], w2b = g_w2[n + 1];
#pragma unroll
        for (int mi = 0; mi < 2; mi++) {
            float v0 = fmaf(acc[mi][ni][0], INV_S, b1a);
            float v1 = fmaf(acc[mi][ni][1], INV_S, b1b);
            float v2 = fmaf(acc[mi][ni][2], INV_S, b1a);
            float v3 = fmaf(acc[mi][ni][3], INV_S, b1b);
            rs[mi * 2 + 0] += fmaxf(v0, 0.f) * w2a + fmaxf(v1, 0.f) * w2b;
            rs[mi * 2 + 1] += fmaxf(v2, 0.f) * w2a + fmaxf(v3, 0.f) * w2b;
        }
    }
#pragma unroll
    for (int i = 0; i < 4; i++) {
        rs[i] += __shfl_xor_sync(0xffffffffu, rs[i], 1);
        rs[i] += __shfl_xor_sync(0xffffffffu, rs[i], 2);
    }
    if (qcol == 0) {
#pragma unroll
        for (int mi = 0; mi < 2; mi++) {
            atomicAdd(&g_logits[m0 + wm * 32 + mi * 16 + qrow],     rs[mi * 2 + 0]);
            atomicAdd(&g_logits[m0 + wm * 32 + mi * 16 + 8 + qrow], rs[mi * 2 + 1]);
        }
    }
}

// ---------------- finalize ----------------
__global__ void finalize(const float* __restrict__ b2, float* __restrict__ out) {
    int i = blockIdx.x * blockDim.x + threadIdx.x;
    if (i < BATCH) {
        float z = g_logits[i] + b2[0];
        out[i] = 1.0f / (1.0f + expf(-z));
    }
}

// ---------------- launch ----------------
extern "C" void kernel_launch(void* const* d_in, const int* in_sizes, int n_in,
                              void* d_out, int out_size) {
    const float* sim = (const float*)d_in[0];
    const float* W1  = (const float*)d_in[1];
    const float* b1  = (const float*)d_in[2];
    const float* W2  = (const float*)d_in[3];
    const float* b2  = (const float*)d_in[4];
    float* out = (float*)d_out;

    cudaFuncSetAttribute(gemm_fp8, cudaFuncAttributeMaxDynamicSharedMemorySize, SMEM_TOTAL);

    prep_small<<<(BATCH + 255) / 256, 256>>>(b1, W2);
    prep_w18<<<dim3((KP / 4 + 255) / 256, NP), 256>>>(W1);
    triu8<<<BATCH, 256>>>(sim);
    gemm_fp8<<<dim3(NP / 128, BATCH / 128), 256, SMEM_TOTAL>>>();
    finalize<<<(BATCH + 255) / 256, 256>>>(b2, out);
}